// round 16
// baseline (speedup 1.0000x reference)
#include <cuda_runtime.h>
#include <math.h>

#define MDIM 512
#define LDIM 31
#define CTOT 542                 // MDIM + LDIM - 1
#define NX   1024
#define ROWE (NX * LDIM)         // 31744 floats per input row strip
#define ROW4 (ROWE / 4)          // 7936 float4 per row strip
#define XCE  (MDIM * LDIM)       // 15872 floats per H/out row strip
#define XC4  (XCE / 4)           // 3968 float4 per row

#define WC     64                // output columns per tile
#define NTILE  (MDIM / WC)       // 8
#define WCOLS  (2 * WC + 2)      // 130 input cols per window
#define WF4    1008              // float4 loads per stream
#define YLEN   94                // outputs per tile (WC + LDIM - 1)
#define YPAD   96

// dynamic smem layout for bwd kernels: sv[XCE] | sE[CTOT+2] | sred[32]
#define BWD_SMEM ((XCE + CTOT + 2 + 32) * sizeof(float))

// Static scratch (zero-initialized; counters self-reset each launch)
__device__ float    g_ynp[NTILE * MDIM * YPAD]; // per-tile partial yn
__device__ float    g_yn[MDIM * CTOT];
__device__ float    g_rmax1[MDIM];
__device__ float    g_rmax2[MDIM];
__device__ float    g_sinv[2];                  // [0]=1/max(yn), [1]=1/max(X2)
__device__ unsigned g_cnt[2];                   // arrival counters

__device__ __forceinline__ float blockReduceMax(float v, float* sred) {
    __syncthreads();
    int lane = threadIdx.x & 31, wid = threadIdx.x >> 5;
    int nw = blockDim.x >> 5;
    #pragma unroll
    for (int o = 16; o; o >>= 1) v = fmaxf(v, __shfl_xor_sync(0xffffffffu, v, o));
    if (lane == 0) sred[wid] = v;
    __syncthreads();
    if (wid == 0) {
        float x = (lane < nw) ? sred[lane] : -INFINITY;
        #pragma unroll
        for (int o = 16; o; o >>= 1) x = fmaxf(x, __shfl_xor_sync(0xffffffffu, x, o));
        if (lane == 0) sred[0] = x;
    }
    __syncthreads();
    return sred[0];
}

// ---------------------------------------------------------------------------
// Forward: one block per (tile, row). Contiguous-window float4 streaming,
// lambda-before-resize, conflict-free skew sum. (unchanged — at DRAM floor)
// ---------------------------------------------------------------------------
__global__ void __launch_bounds__(256, 6) k_fwd(const float* __restrict__ X,
                                                const float* __restrict__ H) {
    __shared__ float4 sBuf4[WF4];
    __shared__ float  sLam[WCOLS * 32];
    float* sRaw = (float*)sBuf4;
    float* sP   = (float*)sBuf4;

    const int t = blockIdx.x, r = blockIdx.y;
    const int tid = threadIdx.x;
    const int lane = tid & 31, warp = tid >> 5;

    float w0, w1, w2, w3; int i0, i1, i2, i3;
    if (r == 0) {
        w0 = 0.f;     w1 = 3.f/7.f; w2 = 3.f/7.f; w3 = 1.f/7.f;
        i0 = 0; i1 = 0; i2 = 1; i3 = 2;
    } else if (r == MDIM - 1) {
        w0 = 1.f/7.f; w1 = 3.f/7.f; w2 = 3.f/7.f; w3 = 0.f;
        i0 = 2*r - 1; i1 = 2*r; i2 = 2*r + 1; i3 = i2;
    } else {
        w0 = 0.125f;  w1 = 0.375f;  w2 = 0.375f;  w3 = 0.125f;
        i0 = 2*r - 1; i1 = 2*r; i2 = 2*r + 1; i3 = 2*r + 2;
    }
    const float4* X0 = (const float4*)(X + (size_t)i0 * ROWE);
    const float4* X1 = (const float4*)(X + (size_t)i1 * ROWE);
    const float4* X2p = (const float4*)(X + (size_t)i2 * ROWE);
    const float4* X3 = (const float4*)(X + (size_t)i3 * ROWE);
    const float* Hr = H + (size_t)r * XCE;

    {
        const int j0 = 992 * t - 8;
        for (int j = tid; j < WF4; j += 256) {
            int g4 = j0 + j;
            float4 o = make_float4(0.f, 0.f, 0.f, 0.f);
            if (g4 >= 0 && g4 < ROW4) {
                float4 a = __ldg(X0 + g4), b = __ldg(X1 + g4);
                float4 c = __ldg(X2p + g4), d = __ldg(X3 + g4);
                o.x = w0*a.x + w1*b.x + w2*c.x + w3*d.x;
                o.y = w0*a.y + w1*b.y + w2*c.y + w3*d.y;
                o.z = w0*a.z + w1*b.z + w2*c.z + w3*d.z;
                o.w = w0*a.w + w1*b.w + w2*c.w + w3*d.w;
            }
            sBuf4[j] = o;
        }
    }
    __syncthreads();

    for (int col = warp; col < WCOLS; col += 8) {
        float x = (lane < LDIM) ? sRaw[1 + col * LDIM + lane] : 0.f;
        float xm = __shfl_up_sync(0xffffffffu, x, 1);
        float xp = __shfl_down_sync(0xffffffffu, x, 1);
        float v = 0.5f * x;
        if (lane > 0)         v += 0.25f * xm;
        if (lane < LDIM - 1)  v += 0.25f * xp;
        sLam[col * 32 + lane] = v;
    }
    __syncthreads();

    {
        const int c0 = t * WC;
        const int l = lane, dc0 = warp;
        if (l < LDIM) {
            #pragma unroll
            for (int q = 0; q < 8; ++q) {
                int dc = dc0 + q * 8;
                int c = c0 + dc;
                float v;
                if (c == 0) {
                    v = (3.f/7.f)*sLam[1*32 + l] + (3.f/7.f)*sLam[2*32 + l]
                      + (1.f/7.f)*sLam[3*32 + l];
                } else if (c == MDIM - 1) {
                    v = (1.f/7.f)*sLam[126*32 + l] + (3.f/7.f)*sLam[127*32 + l]
                      + (3.f/7.f)*sLam[128*32 + l];
                } else {
                    int b = 2 * dc * 32 + l;
                    v = 0.125f*sLam[b]      + 0.375f*sLam[b + 32]
                      + 0.375f*sLam[b + 64] + 0.125f*sLam[b + 96];
                }
                sP[dc * 33 + l] = __ldg(Hr + c * LDIM + l) * v;
            }
        }
    }
    __syncthreads();

    if (tid < YLEN) {
        int lcc = tid;
        int ilo = lcc - (WC - 1); if (ilo < 0) ilo = 0;
        int ihi = (lcc < LDIM - 1) ? lcc : (LDIM - 1);
        float acc = 0.f;
        for (int i = ilo; i <= ihi; ++i)
            acc += sP[(lcc - i) * 33 + i];
        g_ynp[(t * MDIM + r) * YPAD + lcc] = acc;
    }
}

// ---------------------------------------------------------------------------
// Combine tile partials -> yn row + per-row max; last block reduces the 512
// row maxes to the scalar g_sinv[0] (threadFenceReduction pattern,
// deterministic: one block, fixed order).
// ---------------------------------------------------------------------------
__global__ void __launch_bounds__(256) k_max(void) {
    __shared__ float sred[32];
    __shared__ unsigned lastFlag;
    const int r = blockIdx.x, tid = threadIdx.x;
    float lmax = -INFINITY;
    for (int cc = tid; cc < CTOT; cc += 256) {
        int thi = cc >> 6; if (thi > NTILE - 1) thi = NTILE - 1;
        int tlo = (cc - 30) >> 6; if (tlo < 0) tlo = 0;
        float s = 0.f;
        for (int t2 = tlo; t2 <= thi; ++t2)
            s += g_ynp[(t2 * MDIM + r) * YPAD + (cc - (t2 << 6))];
        g_yn[r * CTOT + cc] = s;
        lmax = fmaxf(lmax, s);
    }
    float bm = blockReduceMax(lmax, sred);
    if (tid == 0) {
        g_rmax1[r] = bm;
        __threadfence();
        lastFlag = (atomicAdd(&g_cnt[0], 1u) == MDIM - 1) ? 1u : 0u;
    }
    __syncthreads();
    if (lastFlag) {
        float v = fmaxf(g_rmax1[tid], g_rmax1[tid + 256]);
        float gm = blockReduceMax(v, sred);
        if (tid == 0) { g_sinv[0] = 1.0f / gm; g_cnt[0] = 0u; }
    }
}

// Build scaled residual sE (zero-padded) and the full-row multiplier array
// sv directly from sE. 512 threads = one m each; stride-31 stores (conflict-free).
__device__ __forceinline__ void buildRowV(const float* __restrict__ y, int r,
                                          float invY, float scale,
                                          float* sE, float* sv) {
    const float* ynr = g_yn + r * CTOT;
    const float* yr  = y + r * CTOT;
    const int tid = threadIdx.x;
    if (tid == 0) { sE[0] = 0.f; sE[CTOT + 1] = 0.f; }
    for (int cc = tid; cc < CTOT; cc += 512)
        sE[cc + 1] = (ynr[cc] * invY - yr[cc]) * scale;
    __syncthreads();
    const float* base = sE + tid;        // thread tid handles m = tid
    float* svm = sv + tid * LDIM;
    #pragma unroll
    for (int i = 0; i < LDIM; ++i)
        svm[i] = 0.25f * (base[i] + base[i + 2]) + 0.5f * base[i + 1];
    svm[0]        -= 0.25f * base[0];
    svm[LDIM - 1] -= 0.25f * base[32];
    __syncthreads();
}

// ---------------------------------------------------------------------------
// Backward pass 1: per-row max of X2; last block reduces to g_sinv[1].
// ---------------------------------------------------------------------------
__global__ void __launch_bounds__(512) k_bwd1(const float* __restrict__ y,
                                              const float* __restrict__ H) {
    extern __shared__ float sm[];
    float* sv   = sm;
    float* sE   = sm + XCE;
    float* sred = sE + CTOT + 2;
    __shared__ unsigned lastFlag;
    const int r = blockIdx.x, tid = threadIdx.x;

    const float invY = g_sinv[0];
    buildRowV(y, r, invY, 1.0f, sE, sv);

    const float4* H4 = (const float4*)(H + (size_t)r * XCE);
    const float4* V4 = (const float4*)sv;
    float lmax = -INFINITY;
    #pragma unroll 4
    for (int j = tid; j < XC4; j += 512) {
        float4 h = __ldg(H4 + j);
        float4 v = V4[j];
        lmax = fmaxf(lmax, fmaxf(fmaxf(h.x * v.x, h.y * v.y),
                                 fmaxf(h.z * v.z, h.w * v.w)));
    }
    float bm = blockReduceMax(lmax, sred);
    if (tid == 0) {
        g_rmax2[r] = bm;
        __threadfence();
        lastFlag = (atomicAdd(&g_cnt[1], 1u) == MDIM - 1) ? 1u : 0u;
    }
    __syncthreads();
    if (lastFlag) {
        float v = (tid < MDIM) ? g_rmax2[tid] : -INFINITY;
        float gm = blockReduceMax(v, sred);
        if (tid == 0) { g_sinv[1] = 1.0f / gm; g_cnt[1] = 0u; }
    }
}

// ---------------------------------------------------------------------------
// Backward pass 2: normalized output; both maxes are precomputed scalars.
// ---------------------------------------------------------------------------
__global__ void __launch_bounds__(512) k_bwd2(const float* __restrict__ y,
                                              const float* __restrict__ H,
                                              float* __restrict__ out) {
    extern __shared__ float sm[];
    float* sv = sm;
    float* sE = sm + XCE;
    const int r = blockIdx.x, tid = threadIdx.x;

    const float invY = g_sinv[0];
    const float invO = g_sinv[1];
    buildRowV(y, r, invY, invO, sE, sv);

    const float4* H4 = (const float4*)(H + (size_t)r * XCE);
    float4*       O4 = (float4*)(out + (size_t)r * XCE);
    const float4* V4 = (const float4*)sv;
    #pragma unroll 4
    for (int j = tid; j < XC4; j += 512) {
        float4 h = __ldg(H4 + j);
        float4 v = V4[j];
        float4 o;
        o.x = h.x * v.x; o.y = h.y * v.y; o.z = h.z * v.z; o.w = h.w * v.w;
        O4[j] = o;
    }
}

extern "C" void kernel_launch(void* const* d_in, const int* in_sizes, int n_in,
                              void* d_out, int out_size) {
    const float *X = 0, *y = 0, *H = 0;
    for (int i = 0; i < n_in; ++i) {
        if      (in_sizes[i] == NX * NX * LDIM)     X = (const float*)d_in[i];
        else if (in_sizes[i] == MDIM * CTOT)        y = (const float*)d_in[i];
        else if (in_sizes[i] == MDIM * MDIM * LDIM) H = (const float*)d_in[i];
    }
    if (!X || !y || !H) {
        X = (const float*)d_in[0];
        y = (const float*)d_in[1];
        H = (const float*)d_in[2];
    }
    float* out = (float*)d_out;

    cudaFuncSetAttribute(k_bwd1, cudaFuncAttributeMaxDynamicSharedMemorySize,
                         (int)BWD_SMEM);
    cudaFuncSetAttribute(k_bwd2, cudaFuncAttributeMaxDynamicSharedMemorySize,
                         (int)BWD_SMEM);

    dim3 gf(NTILE, MDIM);
    k_fwd <<<gf, 256>>>(X, H);
    k_max <<<MDIM, 256>>>();
    k_bwd1<<<MDIM, 512, BWD_SMEM>>>(y, H);
    k_bwd2<<<MDIM, 512, BWD_SMEM>>>(y, H, out);
}

// round 17
// speedup vs baseline: 1.0076x; 1.0076x over previous
#include <cuda_runtime.h>
#include <math.h>

#define MDIM 512
#define LDIM 31
#define CTOT 542                 // MDIM + LDIM - 1
#define NX   1024
#define ROWE (NX * LDIM)         // 31744 floats per input row strip
#define ROW4 (ROWE / 4)          // 7936 float4 per row strip
#define XCE  (MDIM * LDIM)       // 15872 floats per H/out row strip
#define XC4  (XCE / 4)           // 3968 float4 per row

#define WC     64                // output columns per tile
#define NTILE  (MDIM / WC)       // 8
#define WCOLS  (2 * WC + 2)      // 130 input cols per window
#define WF4    1008              // float4 loads per stream
#define YLEN   94                // outputs per tile (WC + LDIM - 1)
#define YPAD   96

#define NBLK   256               // bwd blocks (2 rows each) — co-resident by design

// dynamic smem for k_bwd: sv[XCE] | sE[CTOT+2] | syn[2*CTOT] | sred[32]
#define BWD_SMEM ((XCE + (CTOT + 2) + 2 * CTOT + 32) * sizeof(float))

// Static scratch (zero-init at load; counters/flags self-reset every launch)
__device__ float             g_ynp[NTILE * MDIM * YPAD];
__device__ float             g_rmax1[MDIM];
__device__ float             g_rmax2[MDIM];
__device__ volatile float    g_sinvV[2];     // [0]=1/max(yn), [1]=1/max(X2)
__device__ unsigned          g_cnt[3];
__device__ volatile unsigned g_flag[2];

__device__ __forceinline__ float blockReduceMax(float v, float* sred) {
    __syncthreads();
    int lane = threadIdx.x & 31, wid = threadIdx.x >> 5;
    int nw = blockDim.x >> 5;
    #pragma unroll
    for (int o = 16; o; o >>= 1) v = fmaxf(v, __shfl_xor_sync(0xffffffffu, v, o));
    if (lane == 0) sred[wid] = v;
    __syncthreads();
    if (wid == 0) {
        float x = (lane < nw) ? sred[lane] : -INFINITY;
        #pragma unroll
        for (int o = 16; o; o >>= 1) x = fmaxf(x, __shfl_xor_sync(0xffffffffu, x, o));
        if (lane == 0) sred[0] = x;
    }
    __syncthreads();
    return sred[0];
}

// ---------------------------------------------------------------------------
// Forward: unchanged (measured at its DRAM floor).
// ---------------------------------------------------------------------------
__global__ void __launch_bounds__(256, 6) k_fwd(const float* __restrict__ X,
                                                const float* __restrict__ H) {
    __shared__ float4 sBuf4[WF4];
    __shared__ float  sLam[WCOLS * 32];
    float* sRaw = (float*)sBuf4;
    float* sP   = (float*)sBuf4;

    const int t = blockIdx.x, r = blockIdx.y;
    const int tid = threadIdx.x;
    const int lane = tid & 31, warp = tid >> 5;

    float w0, w1, w2, w3; int i0, i1, i2, i3;
    if (r == 0) {
        w0 = 0.f;     w1 = 3.f/7.f; w2 = 3.f/7.f; w3 = 1.f/7.f;
        i0 = 0; i1 = 0; i2 = 1; i3 = 2;
    } else if (r == MDIM - 1) {
        w0 = 1.f/7.f; w1 = 3.f/7.f; w2 = 3.f/7.f; w3 = 0.f;
        i0 = 2*r - 1; i1 = 2*r; i2 = 2*r + 1; i3 = i2;
    } else {
        w0 = 0.125f;  w1 = 0.375f;  w2 = 0.375f;  w3 = 0.125f;
        i0 = 2*r - 1; i1 = 2*r; i2 = 2*r + 1; i3 = 2*r + 2;
    }
    const float4* X0 = (const float4*)(X + (size_t)i0 * ROWE);
    const float4* X1 = (const float4*)(X + (size_t)i1 * ROWE);
    const float4* X2p = (const float4*)(X + (size_t)i2 * ROWE);
    const float4* X3 = (const float4*)(X + (size_t)i3 * ROWE);
    const float* Hr = H + (size_t)r * XCE;

    {
        const int j0 = 992 * t - 8;
        for (int j = tid; j < WF4; j += 256) {
            int g4 = j0 + j;
            float4 o = make_float4(0.f, 0.f, 0.f, 0.f);
            if (g4 >= 0 && g4 < ROW4) {
                float4 a = __ldg(X0 + g4), b = __ldg(X1 + g4);
                float4 c = __ldg(X2p + g4), d = __ldg(X3 + g4);
                o.x = w0*a.x + w1*b.x + w2*c.x + w3*d.x;
                o.y = w0*a.y + w1*b.y + w2*c.y + w3*d.y;
                o.z = w0*a.z + w1*b.z + w2*c.z + w3*d.z;
                o.w = w0*a.w + w1*b.w + w2*c.w + w3*d.w;
            }
            sBuf4[j] = o;
        }
    }
    __syncthreads();

    for (int col = warp; col < WCOLS; col += 8) {
        float x = (lane < LDIM) ? sRaw[1 + col * LDIM + lane] : 0.f;
        float xm = __shfl_up_sync(0xffffffffu, x, 1);
        float xp = __shfl_down_sync(0xffffffffu, x, 1);
        float v = 0.5f * x;
        if (lane > 0)         v += 0.25f * xm;
        if (lane < LDIM - 1)  v += 0.25f * xp;
        sLam[col * 32 + lane] = v;
    }
    __syncthreads();

    {
        const int c0 = t * WC;
        const int l = lane, dc0 = warp;
        if (l < LDIM) {
            #pragma unroll
            for (int q = 0; q < 8; ++q) {
                int dc = dc0 + q * 8;
                int c = c0 + dc;
                float v;
                if (c == 0) {
                    v = (3.f/7.f)*sLam[1*32 + l] + (3.f/7.f)*sLam[2*32 + l]
                      + (1.f/7.f)*sLam[3*32 + l];
                } else if (c == MDIM - 1) {
                    v = (1.f/7.f)*sLam[126*32 + l] + (3.f/7.f)*sLam[127*32 + l]
                      + (3.f/7.f)*sLam[128*32 + l];
                } else {
                    int b = 2 * dc * 32 + l;
                    v = 0.125f*sLam[b]      + 0.375f*sLam[b + 32]
                      + 0.375f*sLam[b + 64] + 0.125f*sLam[b + 96];
                }
                sP[dc * 33 + l] = __ldg(Hr + c * LDIM + l) * v;
            }
        }
    }
    __syncthreads();

    if (tid < YLEN) {
        int lcc = tid;
        int ilo = lcc - (WC - 1); if (ilo < 0) ilo = 0;
        int ihi = (lcc < LDIM - 1) ? lcc : (LDIM - 1);
        float acc = 0.f;
        for (int i = ilo; i <= ihi; ++i)
            acc += sP[(lcc - i) * 33 + i];
        g_ynp[(t * MDIM + r) * YPAD + lcc] = acc;
    }
}

// Build scaled residual sE (zero-padded) and multiplier array sv from the
// SMEM-resident yn row. 512 threads = one m each; stride-31 stores.
__device__ __forceinline__ void buildRowV(const float* __restrict__ synRow,
                                          const float* __restrict__ yr,
                                          float invY, float scale,
                                          float* sE, float* sv) {
    const int tid = threadIdx.x;
    if (tid == 0) { sE[0] = 0.f; sE[CTOT + 1] = 0.f; }
    for (int cc = tid; cc < CTOT; cc += 512)
        sE[cc + 1] = (synRow[cc] * invY - yr[cc]) * scale;
    __syncthreads();
    const float* base = sE + tid;
    float* svm = sv + tid * LDIM;
    #pragma unroll
    for (int i = 0; i < LDIM; ++i)
        svm[i] = 0.25f * (base[i] + base[i + 2]) + 0.5f * base[i + 1];
    svm[0]        -= 0.25f * base[0];
    svm[LDIM - 1] -= 0.25f * base[32];
    __syncthreads();
}

// ---------------------------------------------------------------------------
// Fused backward: combine yn partials (SMEM) -> grid barrier (1/maxY) ->
// X2 max pass -> grid barrier (1/maxO) -> normalized output.
// Grid of NBLK=256 blocks is guaranteed co-resident (SMEM=>3/SM, lb(512,2)
// =>>=2/SM, capacity >= 296 > 256), so the spin barriers cannot deadlock.
// All reduced values are produced by ONE block in fixed order: deterministic.
// ---------------------------------------------------------------------------
__global__ void __launch_bounds__(512, 2) k_bwd(const float* __restrict__ y,
                                                const float* __restrict__ H,
                                                float* __restrict__ out) {
    extern __shared__ float sm[];
    float* sv   = sm;                         // XCE
    float* sE   = sv + XCE;                   // CTOT+2
    float* syn  = sE + CTOT + 2;              // 2*CTOT
    float* sred = syn + 2 * CTOT;             // 32
    __shared__ unsigned isLast;
    const int b = blockIdx.x, tid = threadIdx.x;

    // ---- Phase 1: combine tile partials into SMEM yn rows + row maxes ----
    for (int rr = 0; rr < 2; ++rr) {
        const int r = 2 * b + rr;
        float lmax = -INFINITY;
        for (int cc = tid; cc < CTOT; cc += 512) {
            int thi = cc >> 6; if (thi > NTILE - 1) thi = NTILE - 1;
            int tlo = (cc - 30) >> 6; if (tlo < 0) tlo = 0;
            float s = 0.f;
            for (int t2 = tlo; t2 <= thi; ++t2)
                s += __ldg(&g_ynp[(t2 * MDIM + r) * YPAD + (cc - (t2 << 6))]);
            syn[rr * CTOT + cc] = s;
            lmax = fmaxf(lmax, s);
        }
        float bm = blockReduceMax(lmax, sred);
        if (tid == 0) g_rmax1[r] = bm;
    }

    // ---- Grid barrier A: produce g_sinvV[0] = 1/max(yn) ----
    __syncthreads();
    if (tid == 0) { __threadfence(); isLast = (atomicAdd(&g_cnt[0], 1u) == NBLK - 1); }
    __syncthreads();
    if (isLast) {
        float v = __ldcg(&g_rmax1[tid]);                // 512 values, 512 threads
        float gm = blockReduceMax(v, sred);
        if (tid == 0) { g_sinvV[0] = 1.0f / gm; __threadfence(); g_flag[0] = 1u; }
    }
    if (tid == 0) { while (g_flag[0] == 0u) __nanosleep(64); }
    __syncthreads();
    const float invY = g_sinvV[0];

    // ---- Phase 2: X2 max pass for both rows ----
    for (int rr = 0; rr < 2; ++rr) {
        const int r = 2 * b + rr;
        buildRowV(syn + rr * CTOT, y + r * CTOT, invY, 1.0f, sE, sv);
        const float4* H4 = (const float4*)(H + (size_t)r * XCE);
        const float4* V4 = (const float4*)sv;
        float lmax = -INFINITY;
        #pragma unroll 4
        for (int j = tid; j < XC4; j += 512) {
            float4 h = __ldg(H4 + j);
            float4 v = V4[j];
            lmax = fmaxf(lmax, fmaxf(fmaxf(h.x * v.x, h.y * v.y),
                                     fmaxf(h.z * v.z, h.w * v.w)));
        }
        float bm = blockReduceMax(lmax, sred);
        if (tid == 0) g_rmax2[r] = bm;
        __syncthreads();                       // sv/sE dead before next build
    }

    // ---- Grid barrier B: produce g_sinvV[1] = 1/max(X2) ----
    if (tid == 0) { __threadfence(); isLast = (atomicAdd(&g_cnt[1], 1u) == NBLK - 1); }
    __syncthreads();
    if (isLast) {
        float v = __ldcg(&g_rmax2[tid]);
        float gm = blockReduceMax(v, sred);
        if (tid == 0) { g_sinvV[1] = 1.0f / gm; __threadfence(); g_flag[1] = 1u; }
    }
    if (tid == 0) { while (g_flag[1] == 0u) __nanosleep(64); }
    __syncthreads();
    const float invO = g_sinvV[1];

    // ---- Phase 3: normalized output (invO folded into sv) ----
    for (int rr = 0; rr < 2; ++rr) {
        const int r = 2 * b + rr;
        buildRowV(syn + rr * CTOT, y + r * CTOT, invY, invO, sE, sv);
        const float4* H4 = (const float4*)(H + (size_t)r * XCE);
        float4*       O4 = (float4*)(out + (size_t)r * XCE);
        const float4* V4 = (const float4*)sv;
        #pragma unroll 4
        for (int j = tid; j < XC4; j += 512) {
            float4 h = __ldg(H4 + j);
            float4 v = V4[j];
            float4 o;
            o.x = h.x * v.x; o.y = h.y * v.y; o.z = h.z * v.z; o.w = h.w * v.w;
            O4[j] = o;
        }
        __syncthreads();
    }

    // ---- Cleanup: last finisher resets counters/flags for graph replay ----
    if (tid == 0) {
        __threadfence();
        if (atomicAdd(&g_cnt[2], 1u) == NBLK - 1) {
            g_cnt[0] = 0u; g_cnt[1] = 0u; g_cnt[2] = 0u;
            g_flag[0] = 0u; g_flag[1] = 0u;
            __threadfence();
        }
    }
}

extern "C" void kernel_launch(void* const* d_in, const int* in_sizes, int n_in,
                              void* d_out, int out_size) {
    const float *X = 0, *y = 0, *H = 0;
    for (int i = 0; i < n_in; ++i) {
        if      (in_sizes[i] == NX * NX * LDIM)     X = (const float*)d_in[i];
        else if (in_sizes[i] == MDIM * CTOT)        y = (const float*)d_in[i];
        else if (in_sizes[i] == MDIM * MDIM * LDIM) H = (const float*)d_in[i];
    }
    if (!X || !y || !H) {
        X = (const float*)d_in[0];
        y = (const float*)d_in[1];
        H = (const float*)d_in[2];
    }
    float* out = (float*)d_out;

    cudaFuncSetAttribute(k_bwd, cudaFuncAttributeMaxDynamicSharedMemorySize,
                         (int)BWD_SMEM);

    dim3 gf(NTILE, MDIM);
    k_fwd<<<gf, 256>>>(X, H);
    k_bwd<<<NBLK, 512, BWD_SMEM>>>(y, H, out);
}